// round 7
// baseline (speedup 1.0000x reference)
#include <cuda_runtime.h>

// ViT_15358803051012 — 8 elements/block, 16 warps (2 per element).
// Per-element smem (WSM = 3140 floats, stride%32==4):
//   [0..784)    P: patches; then S partials (2x256) B; S2 partials (2x64) D; H at +128 later
//   [784..3136) A: QKV rows [s][48]; layer1 Q|K|V = 0..15|16..31|32..47;
//               tok2->0..15, Q2=16..23, K2=24..31, V2=32..39, tok3=40..47
#define WSM 3140
#define ELEMS 8
#define NWARPS 16

// Interleaved weights: float4 index ((s*12+j)*16 + i4*4 + oq) -> W1(s, o48=4j+oq)[i4*4..+3]
__device__ float d_W1[49 * 12 * 16 * 4];
// bias: d_B1[s*48 + j4*16 + oq*4 + k] = bias(s, o48 = 4*(j4*4+k)+oq)
__device__ float d_B1[49 * 48];
// float4 index ((s*6+j)*16 + i4*4 + oq) -> W2(s, o24=4j+oq)[i4*4..+3]
__device__ float d_W2[49 * 6 * 16 * 4];
__device__ float d_FC1[49 * 2 * 16 * 4]; // [((s*2+h)*16 + o)*4 + j]

__global__ void prep_kernel(const float* __restrict__ pos_emb,
                            const float* __restrict__ WQ1,
                            const float* __restrict__ WK1,
                            const float* __restrict__ WV1,
                            const float* __restrict__ WQ2,
                            const float* __restrict__ WK2,
                            const float* __restrict__ WV2,
                            const float* __restrict__ fc1w) {
    int t = blockIdx.x * blockDim.x + threadIdx.x;
    if (t < 2352) {
        int s = t / 48;
        int o48 = t - s * 48;
        int m = o48 >> 4;
        int o = o48 & 15;
        int j  = o48 >> 2;
        int oq = o48 & 3;
        const float* W = (m == 0) ? WQ1 : (m == 1) ? WK1 : WV1;
        const float* wrow = W + (s * 16 + o) * 32;
        const float* pe = pos_emb + s * 16;
        float bias = 0.f;
#pragma unroll
        for (int i4 = 0; i4 < 4; i4++)
#pragma unroll
            for (int c = 0; c < 4; c++) {
                d_W1[(((s * 12 + j) * 16) + i4 * 4 + oq) * 4 + c] = wrow[i4 * 4 + c];
            }
#pragma unroll
        for (int i = 0; i < 16; i++) bias = fmaf(pe[i], wrow[16 + i], bias);
        int j4 = j >> 2, k = j & 3;
        d_B1[s * 48 + j4 * 16 + oq * 4 + k] = bias;
    } else if (t < 2352 + 1176) {
        int u = t - 2352;
        int s = u / 24;
        int o24 = u - s * 24;
        int m = o24 >> 3;
        int o = o24 & 7;
        int j  = o24 >> 2;
        int oq = o24 & 3;
        const float* W = (m == 0) ? WQ2 : (m == 1) ? WK2 : WV2;
        const float* wrow = W + (s * 8 + o) * 16;
#pragma unroll
        for (int i4 = 0; i4 < 4; i4++)
#pragma unroll
            for (int c = 0; c < 4; c++) {
                d_W2[(((s * 6 + j) * 16) + i4 * 4 + oq) * 4 + c] = wrow[i4 * 4 + c];
            }
    } else if (t < 2352 + 1176 + 6272) {
        int u = t - 3528;          // u = ((s*2+h)*16 + o)*4 + j
        int j = u & 3;
        int r = u >> 2;
        int o = r & 15;
        int sh = r >> 4;
        int h = sh & 1;
        int s = sh >> 1;
        d_FC1[u] = fc1w[o * 392 + s * 8 + h * 4 + j];
    }
}

// strided dot: weight float4s at w4[0], w4[4], w4[8], w4[12]
__device__ __forceinline__ float dot16s(const float* a, const float4* __restrict__ w4, float acc) {
    float4 w0 = w4[0], w1 = w4[4], w2 = w4[8], w3 = w4[12];
    acc = fmaf(a[0],  w0.x, acc); acc = fmaf(a[1],  w0.y, acc);
    acc = fmaf(a[2],  w0.z, acc); acc = fmaf(a[3],  w0.w, acc);
    acc = fmaf(a[4],  w1.x, acc); acc = fmaf(a[5],  w1.y, acc);
    acc = fmaf(a[6],  w1.z, acc); acc = fmaf(a[7],  w1.w, acc);
    acc = fmaf(a[8],  w2.x, acc); acc = fmaf(a[9],  w2.y, acc);
    acc = fmaf(a[10], w2.z, acc); acc = fmaf(a[11], w2.w, acc);
    acc = fmaf(a[12], w3.x, acc); acc = fmaf(a[13], w3.y, acc);
    acc = fmaf(a[14], w3.z, acc); acc = fmaf(a[15], w3.w, acc);
    return acc;
}

__device__ __forceinline__ void pair_sync(int ep) {
    asm volatile("bar.sync %0, 64;" :: "r"(ep + 1) : "memory");
}

__device__ __forceinline__ float4 add4(float4 a, float4 b) {
    a.x += b.x; a.y += b.y; a.z += b.z; a.w += b.w; return a;
}

__global__ __launch_bounds__(NWARPS * 32, 2) void vit_kernel(
    const float* __restrict__ x,
    const float* __restrict__ fc1b,
    const float* __restrict__ fc2w,
    const float* __restrict__ fc2b,
    float* __restrict__ out)
{
    extern __shared__ float smem[];
    const int tid = threadIdx.x;
    const int w   = tid >> 5;
    const int ln  = tid & 31;
    const int ep  = w >> 1;
    const int h   = w & 1;
    const int bElem = blockIdx.x * ELEMS;

    float* P0 = smem + ep * WSM;
    float* A0 = P0 + 784;

    // ---- stage 0: warp pair patchifies its element ----
    {
        const float4* x4 = (const float4*)(x + (size_t)(bElem + ep) * 2352);
        for (int j = ln + h * 32; j < 196; j += 64) {
            float4 rc = x4[j];
            float4 gc = x4[196 + j];
            float4 bc = x4[392 + j];
            float4 g;
            g.x = 0.299f * rc.x + 0.587f * gc.x + 0.114f * bc.x;
            g.y = 0.299f * rc.y + 0.587f * gc.y + 0.114f * bc.y;
            g.z = 0.299f * rc.z + 0.587f * gc.z + 0.114f * bc.z;
            g.w = 0.299f * rc.w + 0.587f * gc.w + 0.114f * bc.w;
            int row = j / 7;
            int pc  = j - row * 7;
            int p   = (row >> 2) * 7 + pc;
            int i   = (row & 3) << 2;
            *(float4*)&P0[p * 16 + i] = g;
        }
    }
    __syncthreads();

    const int e  = ln & 7;
    const int oq = ln >> 3;
    float* Pe = smem + e * WSM;
    float* Ae = Pe + 784;

    // ---- stage A: layer-1 projections; per s: act row once, 12 outputs/lane ----
    for (int s = w; s < 49; s += NWARPS) {
        float a[16];
        const float4* pr = (const float4*)(Pe + s * 16);
        ((float4*)a)[0] = pr[0];
        ((float4*)a)[1] = pr[1];
        ((float4*)a)[2] = pr[2];
        ((float4*)a)[3] = pr[3];
        float barr[12];
        const float4* bb = (const float4*)(d_B1 + s * 48);
        ((float4*)barr)[0] = bb[oq];
        ((float4*)barr)[1] = bb[4 + oq];
        ((float4*)barr)[2] = bb[8 + oq];
        const float4* wbase = ((const float4*)d_W1) + s * 192 + oq;
        float* dst = Ae + s * 48 + oq;
#pragma unroll 4
        for (int j = 0; j < 12; j++) {
            float acc = dot16s(a, wbase + j * 16, barr[j]);
            dst[4 * j] = acc;
        }
    }
    __syncthreads();

    // ---- stage B1: partial S over s-range; each warp does full 16x16 ----
    {
        int e16 = ln & 15;
        int dg  = ln >> 4;                 // 8 d's per lane
        float acc[8];
#pragma unroll
        for (int d = 0; d < 8; d++) acc[d] = 0.f;
        int ss0 = h * 25, ss1 = h ? 49 : 25;
        for (int s = ss0; s < ss1; s++) {
            const float* row = A0 + s * 48;
            float kv = row[16 + e16];
            float4 q0 = *(const float4*)&row[dg * 8];
            float4 q1 = *(const float4*)&row[dg * 8 + 4];
            acc[0] = fmaf(q0.x, kv, acc[0]);
            acc[1] = fmaf(q0.y, kv, acc[1]);
            acc[2] = fmaf(q0.z, kv, acc[2]);
            acc[3] = fmaf(q0.w, kv, acc[3]);
            acc[4] = fmaf(q1.x, kv, acc[4]);
            acc[5] = fmaf(q1.y, kv, acc[5]);
            acc[6] = fmaf(q1.z, kv, acc[6]);
            acc[7] = fmaf(q1.w, kv, acc[7]);
        }
        const float sc = 1.0f / 7.0f;
        float* Sp = P0 + h * 256;
#pragma unroll
        for (int d = 0; d < 8; d++) Sp[(dg * 8 + d) * 16 + e16] = acc[d] * sc;
    }
    pair_sync(ep);

    // ---- stage B2: tok2[s,d] = softmax_d(sum_e S[d,e]*V1[s,e]); pair splits s ----
    {
        int d  = ln & 15;
        int sg = (h << 1) | (ln >> 4);
        unsigned gmask = 0xFFFFu << ((ln >> 4) * 16);
        const float4* Sa = (const float4*)&P0[d * 16];
        const float4* Sb = (const float4*)&P0[256 + d * 16];
        float4 s0 = add4(Sa[0], Sb[0]);
        float4 s1 = add4(Sa[1], Sb[1]);
        float4 s2 = add4(Sa[2], Sb[2]);
        float4 s3 = add4(Sa[3], Sb[3]);
        for (int s = sg; s < 49; s += 4) {
            const float* vr = A0 + s * 48 + 32;
            float4 v0 = *(const float4*)&vr[0];
            float4 v1 = *(const float4*)&vr[4];
            float4 v2 = *(const float4*)&vr[8];
            float4 v3 = *(const float4*)&vr[12];
            float a0 = s0.x * v0.x, a1 = s0.y * v0.y;
            a0 = fmaf(s0.z, v0.z, a0); a1 = fmaf(s0.w, v0.w, a1);
            a0 = fmaf(s1.x, v1.x, a0); a1 = fmaf(s1.y, v1.y, a1);
            a0 = fmaf(s1.z, v1.z, a0); a1 = fmaf(s1.w, v1.w, a1);
            a0 = fmaf(s2.x, v2.x, a0); a1 = fmaf(s2.y, v2.y, a1);
            a0 = fmaf(s2.z, v2.z, a0); a1 = fmaf(s2.w, v2.w, a1);
            a0 = fmaf(s3.x, v3.x, a0); a1 = fmaf(s3.y, v3.y, a1);
            a0 = fmaf(s3.z, v3.z, a0); a1 = fmaf(s3.w, v3.w, a1);
            float acc = a0 + a1;
            float mx = acc;
            mx = fmaxf(mx, __shfl_xor_sync(gmask, mx, 8));
            mx = fmaxf(mx, __shfl_xor_sync(gmask, mx, 4));
            mx = fmaxf(mx, __shfl_xor_sync(gmask, mx, 2));
            mx = fmaxf(mx, __shfl_xor_sync(gmask, mx, 1));
            float ex = __expf(acc - mx);
            float sum = ex;
            sum += __shfl_xor_sync(gmask, sum, 8);
            sum += __shfl_xor_sync(gmask, sum, 4);
            sum += __shfl_xor_sync(gmask, sum, 2);
            sum += __shfl_xor_sync(gmask, sum, 1);
            A0[s * 48 + d] = ex / sum;
        }
    }
    __syncthreads();

    // ---- stage C: layer-2 projections; per s: act row once, 6 outputs/lane ----
    for (int s = w; s < 49; s += NWARPS) {
        float a[16];
        const float4* pr = (const float4*)(Ae + s * 48);
        ((float4*)a)[0] = pr[0];
        ((float4*)a)[1] = pr[1];
        ((float4*)a)[2] = pr[2];
        ((float4*)a)[3] = pr[3];
        const float4* wbase = ((const float4*)d_W2) + s * 96 + oq;
        float* dst = Ae + s * 48 + 16 + oq;
#pragma unroll
        for (int j = 0; j < 6; j++) {
            float acc = dot16s(a, wbase + j * 16, 0.f);
            dst[4 * j] = acc;
        }
    }
    __syncthreads();

    // ---- stage D1: partial S2 over s-range; each warp full 8x8 (2 outputs/lane) ----
    {
        int e8 = ln & 7;
        int d1 = ln >> 3;                  // 0..3; also d1+4
        float acc0 = 0.f, acc1 = 0.f;
        int ss0 = h * 25, ss1 = h ? 49 : 25;
        for (int s = ss0; s < ss1; s++) {
            const float* row = A0 + s * 48;
            float vv = row[24 + e8];
            acc0 = fmaf(row[16 + d1], vv, acc0);
            acc1 = fmaf(row[20 + d1], vv, acc1);
        }
        const float sc = 1.0f / 7.0f;
        P0[h * 64 + d1 * 8 + e8]       = acc0 * sc;
        P0[h * 64 + (d1 + 4) * 8 + e8] = acc1 * sc;
    }
    pair_sync(ep);

    // ---- stage D2: tok3[s,d] = softmax_d(sum_e S2[d,e]*V2[s,e]); pair splits s ----
    {
        int d  = ln & 7;
        int sg = (h << 2) | (ln >> 3);
        unsigned gmask = 0xFFu << ((ln >> 3) * 8);
        const float4* Sa = (const float4*)&P0[d * 8];
        const float4* Sb = (const float4*)&P0[64 + d * 8];
        float4 s0 = add4(Sa[0], Sb[0]);
        float4 s1 = add4(Sa[1], Sb[1]);
        for (int s = sg; s < 49; s += 8) {
            const float* vr = A0 + s * 48 + 32;
            float4 v0 = *(const float4*)&vr[0];
            float4 v1 = *(const float4*)&vr[4];
            float a0 = s0.x * v0.x, a1 = s0.y * v0.y;
            a0 = fmaf(s0.z, v0.z, a0); a1 = fmaf(s0.w, v0.w, a1);
            a0 = fmaf(s1.x, v1.x, a0); a1 = fmaf(s1.y, v1.y, a1);
            a0 = fmaf(s1.z, v1.z, a0); a1 = fmaf(s1.w, v1.w, a1);
            float acc = a0 + a1;
            float mx = acc;
            mx = fmaxf(mx, __shfl_xor_sync(gmask, mx, 4));
            mx = fmaxf(mx, __shfl_xor_sync(gmask, mx, 2));
            mx = fmaxf(mx, __shfl_xor_sync(gmask, mx, 1));
            float ex = __expf(acc - mx);
            float sum = ex;
            sum += __shfl_xor_sync(gmask, sum, 4);
            sum += __shfl_xor_sync(gmask, sum, 2);
            sum += __shfl_xor_sync(gmask, sum, 1);
            A0[s * 48 + 40 + d] = ex / sum;
        }
    }
    pair_sync(ep);

    // ---- stage E: fc1 partials; warp h covers its s-range; raw partial -> P0[128+16h+o] ----
    {
        int o  = ln & 15;
        int hh = ln >> 4;
        int s0 = h * 25;
        int s1 = (h == 0) ? 25 : 49;
        float a0 = 0.f, a1 = 0.f, a2 = 0.f, a3 = 0.f;
        for (int s = s0; s < s1; s++) {
            float4 fv = *(const float4*)&A0[s * 48 + 40 + hh * 4];
            float4 wv = *(const float4*)&d_FC1[((s * 2 + hh) * 16 + o) * 4];
            a0 = fmaf(wv.x, fv.x, a0);
            a1 = fmaf(wv.y, fv.y, a1);
            a2 = fmaf(wv.z, fv.z, a2);
            a3 = fmaf(wv.w, fv.w, a3);
        }
        float acc = (a0 + a1) + (a2 + a3);
        acc += __shfl_xor_sync(0xFFFFFFFFu, acc, 16);
        if (hh == 0) P0[128 + h * 16 + o] = acc;
    }
    pair_sync(ep);

    // ---- fc2 (16 -> 10) + softmax(10), even warp of the pair ----
    if (h == 0) {
        float logit = -1e30f;
        if (ln < 10) {
            const float* wr = fc2w + ln * 16;
            float acc = fc2b[ln];
#pragma unroll
            for (int i = 0; i < 16; i++) {
                float hv = fmaxf(P0[128 + i] + P0[144 + i] + fc1b[i], 0.f);
                acc = fmaf(wr[i], hv, acc);
            }
            logit = acc;
        }
        float mx = logit;
#pragma unroll
        for (int off = 16; off >= 1; off >>= 1)
            mx = fmaxf(mx, __shfl_xor_sync(0xFFFFFFFFu, mx, off));
        float ex = (ln < 10) ? __expf(logit - mx) : 0.f;
        float sum = ex;
#pragma unroll
        for (int off = 16; off >= 1; off >>= 1)
            sum += __shfl_xor_sync(0xFFFFFFFFu, sum, off);
        if (ln < 10) out[(size_t)(bElem + ep) * 10 + ln] = ex / sum;
    }
}

extern "C" void kernel_launch(void* const* d_in, const int* in_sizes, int n_in,
                              void* d_out, int out_size) {
    const float* x    = (const float*)d_in[0];
    const float* pos  = (const float*)d_in[1];
    const float* WQ1  = (const float*)d_in[2];
    const float* WK1  = (const float*)d_in[3];
    const float* WV1  = (const float*)d_in[4];
    const float* WQ2  = (const float*)d_in[5];
    const float* WK2  = (const float*)d_in[6];
    const float* WV2  = (const float*)d_in[7];
    const float* fc1w = (const float*)d_in[8];
    const float* fc1b = (const float*)d_in[9];
    const float* fc2w = (const float*)d_in[10];
    const float* fc2b = (const float*)d_in[11];
    float* out = (float*)d_out;

    prep_kernel<<<39, 256>>>(pos, WQ1, WK1, WV1, WQ2, WK2, WV2, fc1w);

    const int smem_bytes = ELEMS * WSM * (int)sizeof(float);   // 100,480 B
    cudaFuncSetAttribute(vit_kernel, cudaFuncAttributeMaxDynamicSharedMemorySize, smem_bytes);
    vit_kernel<<<16384 / ELEMS, NWARPS * 32, smem_bytes>>>(x, fc1b, fc2w, fc2b, out);
}

// round 12
// speedup vs baseline: 1.0498x; 1.0498x over previous
#include <cuda_runtime.h>

// ViT_15358803051012 — 8 elements/block, 16 warps (2 per element).  R6 base + no-max inner softmax.
// Per-element smem (WSM = 3140 floats, stride%32==4):
//   [0..784)    P: patches (stage 0/A); then S (256) B; S2 (64) D; H partials at +128
//   [784..3136) A: QKV rows [s][48]; layer1 Q|K|V = 0..15|16..31|32..47;
//               tok2->0..15, Q2=16..23, K2=24..31, V2=32..39, tok3=40..47
#define WSM 3140
#define ELEMS 8
#define NWARPS 16

__device__ float d_W1[49 * 48 * 16];     // [(s*48 + o48)*16 + i]
__device__ float d_B1[49 * 48];          // [s*48 + oq*12 + j], o48 = 4j+oq
__device__ float d_W2[49 * 24 * 16];     // [(s*24 + o24)*16 + i]
__device__ float d_FC1[49 * 2 * 16 * 4]; // [((s*2+h)*16 + o)*4 + j]

__global__ void prep_kernel(const float* __restrict__ pos_emb,
                            const float* __restrict__ WQ1,
                            const float* __restrict__ WK1,
                            const float* __restrict__ WV1,
                            const float* __restrict__ WQ2,
                            const float* __restrict__ WK2,
                            const float* __restrict__ WV2,
                            const float* __restrict__ fc1w) {
    int t = blockIdx.x * blockDim.x + threadIdx.x;
    if (t < 2352) {
        int s = t / 48;
        int o48 = t - s * 48;
        int m = o48 >> 4;
        int o = o48 & 15;
        const float* W = (m == 0) ? WQ1 : (m == 1) ? WK1 : WV1;
        const float* wrow = W + (s * 16 + o) * 32;
        const float* pe = pos_emb + s * 16;
        float bias = 0.f;
#pragma unroll
        for (int i = 0; i < 16; i++) {
            d_W1[t * 16 + i] = wrow[i];
            bias = fmaf(pe[i], wrow[16 + i], bias);
        }
        int oq = o48 & 3;
        int j  = o48 >> 2;
        d_B1[s * 48 + oq * 12 + j] = bias;
    } else if (t < 2352 + 1176) {
        int u = t - 2352;
        int s = u / 24;
        int o24 = u - s * 24;
        int m = o24 >> 3;
        int o = o24 & 7;
        const float* W = (m == 0) ? WQ2 : (m == 1) ? WK2 : WV2;
        const float* wrow = W + (s * 8 + o) * 16;
#pragma unroll
        for (int i = 0; i < 16; i++) d_W2[u * 16 + i] = wrow[i];
    } else if (t < 2352 + 1176 + 6272) {
        int u = t - 3528;          // u = ((s*2+h)*16 + o)*4 + j
        int j = u & 3;
        int r = u >> 2;
        int o = r & 15;
        int sh = r >> 4;
        int h = sh & 1;
        int s = sh >> 1;
        d_FC1[u] = fc1w[o * 392 + s * 8 + h * 4 + j];
    }
}

__device__ __forceinline__ float dot16(const float* a, const float4* __restrict__ w4, float acc) {
    float4 w0 = w4[0], w1 = w4[1], w2 = w4[2], w3 = w4[3];
    acc = fmaf(a[0],  w0.x, acc); acc = fmaf(a[1],  w0.y, acc);
    acc = fmaf(a[2],  w0.z, acc); acc = fmaf(a[3],  w0.w, acc);
    acc = fmaf(a[4],  w1.x, acc); acc = fmaf(a[5],  w1.y, acc);
    acc = fmaf(a[6],  w1.z, acc); acc = fmaf(a[7],  w1.w, acc);
    acc = fmaf(a[8],  w2.x, acc); acc = fmaf(a[9],  w2.y, acc);
    acc = fmaf(a[10], w2.z, acc); acc = fmaf(a[11], w2.w, acc);
    acc = fmaf(a[12], w3.x, acc); acc = fmaf(a[13], w3.y, acc);
    acc = fmaf(a[14], w3.z, acc); acc = fmaf(a[15], w3.w, acc);
    return acc;
}

__device__ __forceinline__ void pair_sync(int ep) {
    asm volatile("bar.sync %0, 64;" :: "r"(ep + 1) : "memory");
}

__global__ __launch_bounds__(NWARPS * 32, 2) void vit_kernel(
    const float* __restrict__ x,
    const float* __restrict__ fc1b,
    const float* __restrict__ fc2w,
    const float* __restrict__ fc2b,
    float* __restrict__ out)
{
    extern __shared__ float smem[];
    const int tid = threadIdx.x;
    const int w   = tid >> 5;
    const int ln  = tid & 31;
    const int ep  = w >> 1;        // element index 0..7
    const int h   = w & 1;         // half of the pair
    const int bElem = blockIdx.x * ELEMS;

    float* P0 = smem + ep * WSM;   // own element base
    float* A0 = P0 + 784;          // own element QKV rows

    // ---- stage 0: warp pair patchifies its element ----
    {
        const float4* x4 = (const float4*)(x + (size_t)(bElem + ep) * 2352);
        for (int j = ln + h * 32; j < 196; j += 64) {
            float4 rc = x4[j];
            float4 gc = x4[196 + j];
            float4 bc = x4[392 + j];
            float4 g;
            g.x = 0.299f * rc.x + 0.587f * gc.x + 0.114f * bc.x;
            g.y = 0.299f * rc.y + 0.587f * gc.y + 0.114f * bc.y;
            g.z = 0.299f * rc.z + 0.587f * gc.z + 0.114f * bc.z;
            g.w = 0.299f * rc.w + 0.587f * gc.w + 0.114f * bc.w;
            int row = j / 7;
            int pc  = j - row * 7;
            int p   = (row >> 2) * 7 + pc;
            int i   = (row & 3) << 2;
            *(float4*)&P0[p * 16 + i] = g;
        }
    }
    __syncthreads();

    const int e  = ln & 7;
    const int oq = ln >> 3;
    float* Pe = smem + e * WSM;
    float* Ae = Pe + 784;

    // ---- stage A: layer-1 projections; per s: act row once, 12 outputs/lane ----
    for (int s = w; s < 49; s += NWARPS) {
        float a[16];
        const float4* pr = (const float4*)(Pe + s * 16);
        ((float4*)a)[0] = pr[0];
        ((float4*)a)[1] = pr[1];
        ((float4*)a)[2] = pr[2];
        ((float4*)a)[3] = pr[3];
        float barr[12];
        const float4* bv = (const float4*)(d_B1 + s * 48 + oq * 12);
        ((float4*)barr)[0] = bv[0];
        ((float4*)barr)[1] = bv[1];
        ((float4*)barr)[2] = bv[2];
        const float* wb = d_W1 + (s * 48 + oq) * 16;
        float* dst = Ae + s * 48 + oq;
#pragma unroll 4
        for (int j = 0; j < 12; j++) {
            float acc = dot16(a, (const float4*)(wb + j * 64), barr[j]);
            dst[4 * j] = acc;
        }
    }
    __syncthreads();

    // ---- stage B1: S[d][e] = (1/7) sum_s Q1[s,d]*K1[s,e]; pair splits d ----
    {
        int e16 = ln & 15;
        int dg  = (h << 1) | (ln >> 4);     // 0..3, 4 d's each
        float acc[4];
#pragma unroll
        for (int d = 0; d < 4; d++) acc[d] = 0.f;
        for (int s = 0; s < 49; s++) {
            const float* row = A0 + s * 48;
            float kv = row[16 + e16];
            float4 q = *(const float4*)&row[dg * 4];
            acc[0] = fmaf(q.x, kv, acc[0]);
            acc[1] = fmaf(q.y, kv, acc[1]);
            acc[2] = fmaf(q.z, kv, acc[2]);
            acc[3] = fmaf(q.w, kv, acc[3]);
        }
        const float sc = 1.0f / 7.0f;
#pragma unroll
        for (int d = 0; d < 4; d++) P0[(dg * 4 + d) * 16 + e16] = acc[d] * sc;
    }
    pair_sync(ep);

    // ---- stage B2: tok2[s,d] = softmax_d(sum_e S[d,e]*V1[s,e]); no-max softmax ----
    {
        int d  = ln & 15;
        int sg = (h << 1) | (ln >> 4);
        unsigned gmask = 0xFFFFu << ((ln >> 4) * 16);
        float4 s0 = *(const float4*)&P0[d * 16 + 0];
        float4 s1 = *(const float4*)&P0[d * 16 + 4];
        float4 s2 = *(const float4*)&P0[d * 16 + 8];
        float4 s3 = *(const float4*)&P0[d * 16 + 12];
        for (int s = sg; s < 49; s += 4) {
            const float* vr = A0 + s * 48 + 32;
            float4 v0 = *(const float4*)&vr[0];
            float4 v1 = *(const float4*)&vr[4];
            float4 v2 = *(const float4*)&vr[8];
            float4 v3 = *(const float4*)&vr[12];
            float a0 = s0.x * v0.x, a1 = s0.y * v0.y;
            a0 = fmaf(s0.z, v0.z, a0); a1 = fmaf(s0.w, v0.w, a1);
            a0 = fmaf(s1.x, v1.x, a0); a1 = fmaf(s1.y, v1.y, a1);
            a0 = fmaf(s1.z, v1.z, a0); a1 = fmaf(s1.w, v1.w, a1);
            a0 = fmaf(s2.x, v2.x, a0); a1 = fmaf(s2.y, v2.y, a1);
            a0 = fmaf(s2.z, v2.z, a0); a1 = fmaf(s2.w, v2.w, a1);
            a0 = fmaf(s3.x, v3.x, a0); a1 = fmaf(s3.y, v3.y, a1);
            a0 = fmaf(s3.z, v3.z, a0); a1 = fmaf(s3.w, v3.w, a1);
            float ex = __expf(a0 + a1);
            float sum = ex;
            sum += __shfl_xor_sync(gmask, sum, 8);
            sum += __shfl_xor_sync(gmask, sum, 4);
            sum += __shfl_xor_sync(gmask, sum, 2);
            sum += __shfl_xor_sync(gmask, sum, 1);
            A0[s * 48 + d] = ex / sum;
        }
    }
    __syncthreads();

    // ---- stage C: layer-2 projections; per s: act row once, 6 outputs/lane ----
    for (int s = w; s < 49; s += NWARPS) {
        float a[16];
        const float4* pr = (const float4*)(Ae + s * 48);
        ((float4*)a)[0] = pr[0];
        ((float4*)a)[1] = pr[1];
        ((float4*)a)[2] = pr[2];
        ((float4*)a)[3] = pr[3];
        const float* wb = d_W2 + (s * 24 + oq) * 16;
        float* dst = Ae + s * 48 + 16 + oq;
#pragma unroll
        for (int j = 0; j < 6; j++) {
            float acc = dot16(a, (const float4*)(wb + j * 64), 0.f);
            dst[4 * j] = acc;
        }
    }
    __syncthreads();

    // ---- stage D1: S2[d][e] (8x8); 64 lanes of the pair, one output each ----
    {
        int idx = (h << 5) | ln;
        int d = idx >> 3, e8 = idx & 7;
        float acc = 0.f;
        for (int s = 0; s < 49; s++) {
            const float* row = A0 + s * 48;
            acc = fmaf(row[16 + d], row[24 + e8], acc);
        }
        P0[idx] = acc * (1.0f / 7.0f);
    }
    pair_sync(ep);

    // ---- stage D2: tok3[s,d] = softmax_d(sum_e S2[d,e]*V2[s,e]); no-max softmax ----
    {
        int d  = ln & 7;
        int sg = (h << 2) | (ln >> 3);     // 0..7
        unsigned gmask = 0xFFu << ((ln >> 3) * 8);
        float4 s0 = *(const float4*)&P0[d * 8];
        float4 s1 = *(const float4*)&P0[d * 8 + 4];
        for (int s = sg; s < 49; s += 8) {
            const float* vr = A0 + s * 48 + 32;
            float4 v0 = *(const float4*)&vr[0];
            float4 v1 = *(const float4*)&vr[4];
            float a0 = s0.x * v0.x, a1 = s0.y * v0.y;
            a0 = fmaf(s0.z, v0.z, a0); a1 = fmaf(s0.w, v0.w, a1);
            a0 = fmaf(s1.x, v1.x, a0); a1 = fmaf(s1.y, v1.y, a1);
            a0 = fmaf(s1.z, v1.z, a0); a1 = fmaf(s1.w, v1.w, a1);
            float ex = __expf(a0 + a1);
            float sum = ex;
            sum += __shfl_xor_sync(gmask, sum, 4);
            sum += __shfl_xor_sync(gmask, sum, 2);
            sum += __shfl_xor_sync(gmask, sum, 1);
            A0[s * 48 + 40 + d] = ex / sum;
        }
    }
    pair_sync(ep);

    // ---- stage E: fc1 partials; warp h covers its s-range; raw partial -> P0[128+16h+o] ----
    {
        int o  = ln & 15;
        int hh = ln >> 4;
        int s0 = h * 25;
        int s1 = (h == 0) ? 25 : 49;
        float a0 = 0.f, a1 = 0.f, a2 = 0.f, a3 = 0.f;
        for (int s = s0; s < s1; s++) {
            float4 fv = *(const float4*)&A0[s * 48 + 40 + hh * 4];
            float4 wv = *(const float4*)&d_FC1[((s * 2 + hh) * 16 + o) * 4];
            a0 = fmaf(wv.x, fv.x, a0);
            a1 = fmaf(wv.y, fv.y, a1);
            a2 = fmaf(wv.z, fv.z, a2);
            a3 = fmaf(wv.w, fv.w, a3);
        }
        float acc = (a0 + a1) + (a2 + a3);
        acc += __shfl_xor_sync(0xFFFFFFFFu, acc, 16);
        if (hh == 0) P0[128 + h * 16 + o] = acc;
    }
    pair_sync(ep);

    // ---- fc2 (16 -> 10) + softmax(10), even warp of the pair ----
    if (h == 0) {
        float logit = -1e30f;
        if (ln < 10) {
            const float* wr = fc2w + ln * 16;
            float acc = fc2b[ln];
#pragma unroll
            for (int i = 0; i < 16; i++) {
                float hv = fmaxf(P0[128 + i] + P0[144 + i] + fc1b[i], 0.f);
                acc = fmaf(wr[i], hv, acc);
            }
            logit = acc;
        }
        float mx = logit;
#pragma unroll
        for (int off = 16; off >= 1; off >>= 1)
            mx = fmaxf(mx, __shfl_xor_sync(0xFFFFFFFFu, mx, off));
        float ex = (ln < 10) ? __expf(logit - mx) : 0.f;
        float sum = ex;
#pragma unroll
        for (int off = 16; off >= 1; off >>= 1)
            sum += __shfl_xor_sync(0xFFFFFFFFu, sum, off);
        if (ln < 10) out[(size_t)(bElem + ep) * 10 + ln] = ex / sum;
    }
}

extern "C" void kernel_launch(void* const* d_in, const int* in_sizes, int n_in,
                              void* d_out, int out_size) {
    const float* x    = (const float*)d_in[0];
    const float* pos  = (const float*)d_in[1];
    const float* WQ1  = (const float*)d_in[2];
    const float* WK1  = (const float*)d_in[3];
    const float* WV1  = (const float*)d_in[4];
    const float* WQ2  = (const float*)d_in[5];
    const float* WK2  = (const float*)d_in[6];
    const float* WV2  = (const float*)d_in[7];
    const float* fc1w = (const float*)d_in[8];
    const float* fc1b = (const float*)d_in[9];
    const float* fc2w = (const float*)d_in[10];
    const float* fc2b = (const float*)d_in[11];
    float* out = (float*)d_out;

    prep_kernel<<<39, 256>>>(pos, WQ1, WK1, WV1, WQ2, WK2, WV2, fc1w);

    const int smem_bytes = ELEMS * WSM * (int)sizeof(float);   // 100,480 B
    cudaFuncSetAttribute(vit_kernel, cudaFuncAttributeMaxDynamicSharedMemorySize, smem_bytes);
    vit_kernel<<<16384 / ELEMS, NWARPS * 32, smem_bytes>>>(x, fc1b, fc2w, fc2b, out);
}